// round 1
// baseline (speedup 1.0000x reference)
#include <cuda_runtime.h>

#define EPSV 1e-8f

constexpr int Bb = 64;
constexpr int N0 = 20000, E0 = 200000, M0 = 8000;
constexpr int E1 = 80000,  M1 = 2000;
constexpr int E2 = 20000,  M2 = 500;

// ---- scratch (device globals; no allocation allowed) ----
__device__ float g_xT[N0 * Bb];                 // x transposed to (node, batch)
__device__ int   g_cnt0[M0], g_cnt1[M1], g_cnt2[M2];
__device__ int   g_cur0[M0], g_cur1[M1], g_cur2[M2];
__device__ int   g_rp0[M0 + 1], g_rp1[M1 + 1], g_rp2[M2 + 1];
__device__ int   g_ce0[E0], g_ce1[E1], g_ce2[E2];
__device__ float g_d1[M0 * Bb * 8];             // layer-0 output, layout (node, batch, h)
__device__ float g_d2[M1 * Bb * 8];
__device__ float g_d3[M2 * Bb * 8];

// ---- zero counters/cursors for all layers ----
__global__ void k_zero() {
    int i = blockIdx.x * blockDim.x + threadIdx.x;
    if (i < M0) { g_cnt0[i] = 0; g_cur0[i] = 0; }
    if (i < M1) { g_cnt1[i] = 0; g_cur1[i] = 0; }
    if (i < M2) { g_cnt2[i] = 0; g_cur2[i] = 0; }
}

// ---- transpose x (B, N0) -> g_xT (N0, B): coalesced both sides ----
__global__ void k_transpose(const float* __restrict__ x) {
    __shared__ float tile[32][33];
    int nb = blockIdx.x * 32, bb = blockIdx.y * 32;
#pragma unroll
    for (int i = 0; i < 32; i += 8) {
        int b = bb + threadIdx.y + i;
        int n = nb + threadIdx.x;
        tile[threadIdx.y + i][threadIdx.x] = x[b * N0 + n];
    }
    __syncthreads();
#pragma unroll
    for (int i = 0; i < 32; i += 8) {
        int n = nb + threadIdx.y + i;
        int b = bb + threadIdx.x;
        g_xT[n * Bb + b] = tile[threadIdx.x][threadIdx.y + i];
    }
}

// ---- histogram of dst for all three layers in one launch ----
__global__ void k_hist(const int* __restrict__ d0, const int* __restrict__ d1,
                       const int* __restrict__ d2) {
    int i = blockIdx.x * blockDim.x + threadIdx.x;
    if (i < E0)            atomicAdd(&g_cnt0[d0[i]], 1);
    else if (i < E0 + E1)  atomicAdd(&g_cnt1[d1[i - E0]], 1);
    else if (i < E0 + E1 + E2) atomicAdd(&g_cnt2[d2[i - E0 - E1]], 1);
}

// ---- exclusive scan: one block per layer ----
__global__ void k_scan() {
    const int L = blockIdx.x;
    const int* cnt = (L == 0) ? g_cnt0 : (L == 1) ? g_cnt1 : g_cnt2;
    int* rp        = (L == 0) ? g_rp0  : (L == 1) ? g_rp1  : g_rp2;
    int m          = (L == 0) ? M0     : (L == 1) ? M1     : M2;
    __shared__ int sh[1024];
    __shared__ int carry;
    if (threadIdx.x == 0) { carry = 0; rp[0] = 0; }
    __syncthreads();
    for (int base = 0; base < m; base += 1024) {
        int i = base + (int)threadIdx.x;
        sh[threadIdx.x] = (i < m) ? cnt[i] : 0;
        __syncthreads();
        for (int off = 1; off < 1024; off <<= 1) {
            int t = (threadIdx.x >= (unsigned)off) ? sh[threadIdx.x - off] : 0;
            __syncthreads();
            sh[threadIdx.x] += t;
            __syncthreads();
        }
        if (i < m) rp[i + 1] = carry + sh[threadIdx.x];
        int total = sh[1023];
        __syncthreads();
        if (threadIdx.x == 0) carry += total;
        __syncthreads();
    }
}

// ---- fill CSR edge lists ----
__global__ void k_fill(const int* __restrict__ s0, const int* __restrict__ d0,
                       const int* __restrict__ s1, const int* __restrict__ d1,
                       const int* __restrict__ s2, const int* __restrict__ d2) {
    int i = blockIdx.x * blockDim.x + threadIdx.x;
    if (i < E0) {
        int d = d0[i];
        g_ce0[g_rp0[d] + atomicAdd(&g_cur0[d], 1)] = s0[i];
    } else if (i < E0 + E1) {
        int j = i - E0; int d = d1[j];
        g_ce1[g_rp1[d] + atomicAdd(&g_cur1[d], 1)] = s1[j];
    } else if (i < E0 + E1 + E2) {
        int j = i - E0 - E1; int d = d2[j];
        g_ce2[g_rp2[d] + atomicAdd(&g_cur2[d], 1)] = s2[j];
    }
}

// ---- layer 0: scalar scatter-mean + analytic minmax through W0 + relu ----
// 256 threads = 4 dst nodes x 64 batches
__global__ void k_agg0(const float* __restrict__ W0) {
    int group = threadIdx.x >> 6;
    int b = threadIdx.x & 63;
    int node = blockIdx.x * 4 + group;
    int beg = g_rp0[node], end = g_rp0[node + 1];
    float s = 0.f;
    for (int j = beg; j < end; j++) {
        int src = g_ce0[j];
        s += g_xT[src * Bb + b];
    }
    s *= 1.f / fmaxf((float)(end - beg), 1.f);
    // min/max of s over the 64 batches of this node
    float mn = s, mx = s;
#pragma unroll
    for (int off = 16; off; off >>= 1) {
        mn = fminf(mn, __shfl_xor_sync(0xffffffffu, mn, off));
        mx = fmaxf(mx, __shfl_xor_sync(0xffffffffu, mx, off));
    }
    __shared__ float shmn[4][2], shmx[4][2];
    int wig = b >> 5;
    if ((b & 31) == 0) { shmn[group][wig] = mn; shmx[group][wig] = mx; }
    __syncthreads();
    mn = fminf(shmn[group][0], shmn[group][1]);
    mx = fmaxf(shmx[group][0], shmx[group][1]);
    float out[8];
#pragma unroll
    for (int h = 0; h < 8; h++) {
        float w = W0[h];
        float v = w * s;
        float lo = (w >= 0.f) ? w * mn : w * mx;
        float hi = (w >= 0.f) ? w * mx : w * mn;
        out[h] = fmaxf((v - lo) / (hi - lo + EPSV), 0.f);
    }
    float4* q = (float4*)&g_d1[(node * Bb + b) * 8];
    q[0] = make_float4(out[0], out[1], out[2], out[3]);
    q[1] = make_float4(out[4], out[5], out[6], out[7]);
}

// ---- layers 1/2: 8-vector scatter-mean, W after mean, minmax over batch, relu ----
// 128 threads = 2 dst nodes x 64 batches
__global__ void k_aggL(const float* __restrict__ W, int L) {
    const int*   rp   = (L == 1) ? g_rp1 : g_rp2;
    const int*   ce   = (L == 1) ? g_ce1 : g_ce2;
    const float* din  = (L == 1) ? g_d1  : g_d2;
    float*       dout = (L == 1) ? g_d2  : g_d3;
    int group = threadIdx.x >> 6;
    int b = threadIdx.x & 63;
    int node = blockIdx.x * 2 + group;
    __shared__ float sW[64];
    if (threadIdx.x < 64) sW[threadIdx.x] = W[threadIdx.x];
    __syncthreads();
    int beg = rp[node], end = rp[node + 1];
    float acc[8];
#pragma unroll
    for (int h = 0; h < 8; h++) acc[h] = 0.f;
    for (int j = beg; j < end; j++) {
        int src = ce[j];
        const float4* p = (const float4*)&din[(src * Bb + b) * 8];
        float4 a = p[0], c = p[1];
        acc[0] += a.x; acc[1] += a.y; acc[2] += a.z; acc[3] += a.w;
        acc[4] += c.x; acc[5] += c.y; acc[6] += c.z; acc[7] += c.w;
    }
    float inv = 1.f / fmaxf((float)(end - beg), 1.f);
    float t[8], mn[8], mx[8];
#pragma unroll
    for (int h = 0; h < 8; h++) {
        float v = 0.f;
#pragma unroll
        for (int d = 0; d < 8; d++) v += sW[h * 8 + d] * acc[d];
        t[h] = v * inv;
        mn[h] = t[h]; mx[h] = t[h];
    }
#pragma unroll
    for (int off = 16; off; off >>= 1) {
#pragma unroll
        for (int h = 0; h < 8; h++) {
            mn[h] = fminf(mn[h], __shfl_xor_sync(0xffffffffu, mn[h], off));
            mx[h] = fmaxf(mx[h], __shfl_xor_sync(0xffffffffu, mx[h], off));
        }
    }
    __shared__ float smn[2][2][8], smx[2][2][8];
    int wig = b >> 5;
    if ((b & 31) == 0) {
#pragma unroll
        for (int h = 0; h < 8; h++) { smn[group][wig][h] = mn[h]; smx[group][wig][h] = mx[h]; }
    }
    __syncthreads();
    float out[8];
#pragma unroll
    for (int h = 0; h < 8; h++) {
        float lo = fminf(smn[group][0][h], smn[group][1][h]);
        float hi = fmaxf(smx[group][0][h], smx[group][1][h]);
        out[h] = fmaxf((t[h] - lo) / (hi - lo + EPSV), 0.f);
    }
    float4* q = (float4*)&dout[(node * Bb + b) * 8];
    q[0] = make_float4(out[0], out[1], out[2], out[3]);
    q[1] = make_float4(out[4], out[5], out[6], out[7]);
}

// ---- final dot: out[b] = sum_{m,h} d3[m,b,h] * Wout[m*8+h] + bout ----
__global__ void k_out(const float* __restrict__ Wout, const float* __restrict__ bout,
                      float* __restrict__ out) {
    int b = blockIdx.x;
    float p = 0.f;
    for (int idx = threadIdx.x; idx < M2 * 8; idx += blockDim.x) {
        int m = idx >> 3, h = idx & 7;
        p += g_d3[(m * Bb + b) * 8 + h] * Wout[idx];
    }
    __shared__ float sh[128];
    sh[threadIdx.x] = p;
    __syncthreads();
    for (int s = 64; s; s >>= 1) {
        if (threadIdx.x < (unsigned)s) sh[threadIdx.x] += sh[threadIdx.x + s];
        __syncthreads();
    }
    if (threadIdx.x == 0) out[b] = sh[0] + bout[0];
}

extern "C" void kernel_launch(void* const* d_in, const int* in_sizes, int n_in,
                              void* d_out, int out_size) {
    const float* x    = (const float*)d_in[0];
    const int*   e0s  = (const int*)d_in[1];
    const int*   e0d  = (const int*)d_in[2];
    const int*   e1s  = (const int*)d_in[3];
    const int*   e1d  = (const int*)d_in[4];
    const int*   e2s  = (const int*)d_in[5];
    const int*   e2d  = (const int*)d_in[6];
    const float* W0   = (const float*)d_in[7];
    const float* W1   = (const float*)d_in[8];
    const float* W2   = (const float*)d_in[9];
    const float* Wout = (const float*)d_in[10];
    const float* bout = (const float*)d_in[11];
    float* out = (float*)d_out;

    k_zero<<<(M0 + 255) / 256, 256>>>();
    k_transpose<<<dim3(N0 / 32, Bb / 32), dim3(32, 8)>>>(x);
    k_hist<<<(E0 + E1 + E2 + 255) / 256, 256>>>(e0d, e1d, e2d);
    k_scan<<<3, 1024>>>();
    k_fill<<<(E0 + E1 + E2 + 255) / 256, 256>>>(e0s, e0d, e1s, e1d, e2s, e2d);
    k_agg0<<<M0 / 4, 256>>>(W0);
    k_aggL<<<M1 / 2, 128>>>(W1, 1);
    k_aggL<<<M2 / 2, 128>>>(W2, 2);
    k_out<<<Bb, 128>>>(Wout, bout, out);
}

// round 2
// speedup vs baseline: 1.0852x; 1.0852x over previous
#include <cuda_runtime.h>
#include <cuda_fp16.h>

#define EPSV 1e-8f

constexpr int Bb = 64;
constexpr int N0 = 20000, E0 = 200000, M0 = 8000;
constexpr int E1 = 80000,  M1 = 2000;
constexpr int E2 = 20000,  M2 = 500;
constexpr int AUX_N = (M0 + M1 + M2) * 2;   // counters + cursors

// ---- scratch (device globals; no allocation allowed) ----
__device__ __half g_xT[N0 * Bb];            // x transposed to (node, batch), fp16
__device__ int    g_aux[AUX_N];             // [0,10500): cnt  [10500,21000): cur
__device__ int    g_rp0[M0 + 1], g_rp1[M1 + 1], g_rp2[M2 + 1];
__device__ int    g_ce0[E0], g_ce1[E1], g_ce2[E2];
__device__ __half g_d1[M0 * Bb * 8];        // layer-0 out, (node, batch, h), fp16
__device__ __half g_d2[M1 * Bb * 8];
__device__ float  g_d3[M2 * Bb * 8];        // final layer kept fp32

// ---- transpose x (B, N0) -> g_xT (N0, B) fp16; also zero the aux counters ----
__global__ void k_transpose(const float* __restrict__ x) {
    // fused zeroing of counters/cursors
    int gid = (blockIdx.y * gridDim.x + blockIdx.x) * 256 + threadIdx.y * 32 + threadIdx.x;
    if (gid < AUX_N) g_aux[gid] = 0;

    __shared__ float tile[32][33];
    int nb = blockIdx.x * 32, bb = blockIdx.y * 32;
#pragma unroll
    for (int i = 0; i < 32; i += 8) {
        int b = bb + threadIdx.y + i;
        int n = nb + threadIdx.x;
        tile[threadIdx.y + i][threadIdx.x] = x[b * N0 + n];
    }
    __syncthreads();
#pragma unroll
    for (int i = 0; i < 32; i += 8) {
        int n = nb + threadIdx.y + i;
        int b = bb + threadIdx.x;
        g_xT[n * Bb + b] = __float2half_rn(tile[threadIdx.x][threadIdx.y + i]);
    }
}

// ---- histogram of dst for all three layers in one launch ----
__global__ void k_hist(const int* __restrict__ d0, const int* __restrict__ d1,
                       const int* __restrict__ d2) {
    int i = blockIdx.x * blockDim.x + threadIdx.x;
    if (i < E0)                 atomicAdd(&g_aux[d0[i]], 1);
    else if (i < E0 + E1)       atomicAdd(&g_aux[M0 + d1[i - E0]], 1);
    else if (i < E0 + E1 + E2)  atomicAdd(&g_aux[M0 + M1 + d2[i - E0 - E1]], 1);
}

// ---- exclusive scan, warp-shuffle based: one block per layer, 8 elems/thread ----
__global__ void k_scan() {
    const int L = blockIdx.x;
    const int* cnt = (L == 0) ? g_aux : (L == 1) ? g_aux + M0 : g_aux + M0 + M1;
    int* rp        = (L == 0) ? g_rp0 : (L == 1) ? g_rp1     : g_rp2;
    const int m    = (L == 0) ? M0    : (L == 1) ? M1        : M2;

    int t = threadIdx.x;
    int base = t * 8;
    int v[8];
    int s = 0;
#pragma unroll
    for (int k = 0; k < 8; k++) {
        int c = (base + k < m) ? cnt[base + k] : 0;
        s += c;
        v[k] = s;                       // inclusive prefix within thread
    }
    int lane = t & 31, wid = t >> 5;
    // inclusive warp scan of per-thread totals
    int inc = s;
#pragma unroll
    for (int off = 1; off < 32; off <<= 1) {
        int n = __shfl_up_sync(0xffffffffu, inc, off);
        if (lane >= off) inc += n;
    }
    int wexcl = inc - s;                // exclusive prefix within warp
    __shared__ int wtot[32];
    if (lane == 31) wtot[wid] = inc;
    __syncthreads();
    if (t < 32) {
        int w = wtot[t];
        int wi = w;
#pragma unroll
        for (int off = 1; off < 32; off <<= 1) {
            int n = __shfl_up_sync(0xffffffffu, wi, off);
            if (t >= off) wi += n;
        }
        wtot[t] = wi - w;               // exclusive prefix of warp totals
    }
    __syncthreads();
    int off0 = wtot[wid] + wexcl;
#pragma unroll
    for (int k = 0; k < 8; k++)
        if (base + k < m) rp[base + k + 1] = off0 + v[k];
    if (t == 0) rp[0] = 0;
}

// ---- fill CSR edge lists ----
__global__ void k_fill(const int* __restrict__ s0, const int* __restrict__ d0,
                       const int* __restrict__ s1, const int* __restrict__ d1,
                       const int* __restrict__ s2, const int* __restrict__ d2) {
    int* cur = g_aux + (M0 + M1 + M2);
    int i = blockIdx.x * blockDim.x + threadIdx.x;
    if (i < E0) {
        int d = d0[i];
        g_ce0[g_rp0[d] + atomicAdd(&cur[d], 1)] = s0[i];
    } else if (i < E0 + E1) {
        int j = i - E0; int d = d1[j];
        g_ce1[g_rp1[d] + atomicAdd(&cur[M0 + d], 1)] = s1[j];
    } else if (i < E0 + E1 + E2) {
        int j = i - E0 - E1; int d = d2[j];
        g_ce2[g_rp2[d] + atomicAdd(&cur[M0 + M1 + d], 1)] = s2[j];
    }
}

// ---- layer 0: scalar scatter-mean + analytic minmax through W0 + relu ----
// 256 threads = 4 dst nodes x 64 batches
__global__ void k_agg0(const float* __restrict__ W0) {
    int group = threadIdx.x >> 6;
    int b = threadIdx.x & 63;
    int node = blockIdx.x * 4 + group;
    int beg = g_rp0[node], end = g_rp0[node + 1];
    float s = 0.f;
    for (int j = beg; j < end; j++) {
        int src = g_ce0[j];
        s += __half2float(g_xT[src * Bb + b]);
    }
    s *= 1.f / fmaxf((float)(end - beg), 1.f);
    float mn = s, mx = s;
#pragma unroll
    for (int off = 16; off; off >>= 1) {
        mn = fminf(mn, __shfl_xor_sync(0xffffffffu, mn, off));
        mx = fmaxf(mx, __shfl_xor_sync(0xffffffffu, mx, off));
    }
    __shared__ float shmn[4][2], shmx[4][2];
    int wig = b >> 5;
    if ((b & 31) == 0) { shmn[group][wig] = mn; shmx[group][wig] = mx; }
    __syncthreads();
    mn = fminf(shmn[group][0], shmn[group][1]);
    mx = fmaxf(shmx[group][0], shmx[group][1]);
    __half2 out[4];
#pragma unroll
    for (int h = 0; h < 4; h++) {
        float w0 = W0[2 * h], w1 = W0[2 * h + 1];
        float lo0 = (w0 >= 0.f) ? w0 * mn : w0 * mx;
        float hi0 = (w0 >= 0.f) ? w0 * mx : w0 * mn;
        float lo1 = (w1 >= 0.f) ? w1 * mn : w1 * mx;
        float hi1 = (w1 >= 0.f) ? w1 * mx : w1 * mn;
        float r0 = fmaxf((w0 * s - lo0) / (hi0 - lo0 + EPSV), 0.f);
        float r1 = fmaxf((w1 * s - lo1) / (hi1 - lo1 + EPSV), 0.f);
        out[h] = __floats2half2_rn(r0, r1);
    }
    *(uint4*)&g_d1[(node * Bb + b) * 8] = *(uint4*)out;
}

// ---- layers 1/2: 8-vector scatter-mean, W after mean, minmax over batch, relu ----
// 128 threads = 2 dst nodes x 64 batches
__global__ void k_aggL(const float* __restrict__ W, int L) {
    const int*    rp  = (L == 1) ? g_rp1 : g_rp2;
    const int*    ce  = (L == 1) ? g_ce1 : g_ce2;
    const __half* din = (L == 1) ? g_d1  : g_d2;
    int group = threadIdx.x >> 6;
    int b = threadIdx.x & 63;
    int node = blockIdx.x * 2 + group;
    __shared__ float sW[64];
    if (threadIdx.x < 64) sW[threadIdx.x] = W[threadIdx.x];
    __syncthreads();
    int beg = rp[node], end = rp[node + 1];
    float acc[8];
#pragma unroll
    for (int h = 0; h < 8; h++) acc[h] = 0.f;
    for (int j = beg; j < end; j++) {
        int src = ce[j];
        uint4 raw = *(const uint4*)&din[(src * Bb + b) * 8];
        float2 f0 = __half22float2(*(__half2*)&raw.x);
        float2 f1 = __half22float2(*(__half2*)&raw.y);
        float2 f2 = __half22float2(*(__half2*)&raw.z);
        float2 f3 = __half22float2(*(__half2*)&raw.w);
        acc[0] += f0.x; acc[1] += f0.y; acc[2] += f1.x; acc[3] += f1.y;
        acc[4] += f2.x; acc[5] += f2.y; acc[6] += f3.x; acc[7] += f3.y;
    }
    float inv = 1.f / fmaxf((float)(end - beg), 1.f);
    float t[8], mn[8], mx[8];
#pragma unroll
    for (int h = 0; h < 8; h++) {
        float v = 0.f;
#pragma unroll
        for (int d = 0; d < 8; d++) v += sW[h * 8 + d] * acc[d];
        t[h] = v * inv;
        mn[h] = t[h]; mx[h] = t[h];
    }
#pragma unroll
    for (int off = 16; off; off >>= 1) {
#pragma unroll
        for (int h = 0; h < 8; h++) {
            mn[h] = fminf(mn[h], __shfl_xor_sync(0xffffffffu, mn[h], off));
            mx[h] = fmaxf(mx[h], __shfl_xor_sync(0xffffffffu, mx[h], off));
        }
    }
    __shared__ float smn[2][2][8], smx[2][2][8];
    int wig = b >> 5;
    if ((b & 31) == 0) {
#pragma unroll
        for (int h = 0; h < 8; h++) { smn[group][wig][h] = mn[h]; smx[group][wig][h] = mx[h]; }
    }
    __syncthreads();
    float out[8];
#pragma unroll
    for (int h = 0; h < 8; h++) {
        float lo = fminf(smn[group][0][h], smn[group][1][h]);
        float hi = fmaxf(smx[group][0][h], smx[group][1][h]);
        out[h] = fmaxf((t[h] - lo) / (hi - lo + EPSV), 0.f);
    }
    if (L == 1) {
        __half2 p[4];
#pragma unroll
        for (int h = 0; h < 4; h++) p[h] = __floats2half2_rn(out[2 * h], out[2 * h + 1]);
        *(uint4*)&g_d2[(node * Bb + b) * 8] = *(uint4*)p;
    } else {
        float4* q = (float4*)&g_d3[(node * Bb + b) * 8];
        q[0] = make_float4(out[0], out[1], out[2], out[3]);
        q[1] = make_float4(out[4], out[5], out[6], out[7]);
    }
}

// ---- final dot: out[b] = sum_{m,h} d3[m,b,h] * Wout[m*8+h] + bout ----
__global__ void k_out(const float* __restrict__ Wout, const float* __restrict__ bout,
                      float* __restrict__ out) {
    int b = blockIdx.x;
    float p = 0.f;
    for (int idx = threadIdx.x; idx < M2 * 8; idx += blockDim.x) {
        int m = idx >> 3, h = idx & 7;
        p += g_d3[(m * Bb + b) * 8 + h] * Wout[idx];
    }
    __shared__ float sh[128];
    sh[threadIdx.x] = p;
    __syncthreads();
    for (int s = 64; s; s >>= 1) {
        if (threadIdx.x < (unsigned)s) sh[threadIdx.x] += sh[threadIdx.x + s];
        __syncthreads();
    }
    if (threadIdx.x == 0) out[b] = sh[0] + bout[0];
}

extern "C" void kernel_launch(void* const* d_in, const int* in_sizes, int n_in,
                              void* d_out, int out_size) {
    const float* x    = (const float*)d_in[0];
    const int*   e0s  = (const int*)d_in[1];
    const int*   e0d  = (const int*)d_in[2];
    const int*   e1s  = (const int*)d_in[3];
    const int*   e1d  = (const int*)d_in[4];
    const int*   e2s  = (const int*)d_in[5];
    const int*   e2d  = (const int*)d_in[6];
    const float* W0   = (const float*)d_in[7];
    const float* W1   = (const float*)d_in[8];
    const float* W2   = (const float*)d_in[9];
    const float* Wout = (const float*)d_in[10];
    const float* bout = (const float*)d_in[11];
    float* out = (float*)d_out;

    k_transpose<<<dim3(N0 / 32, Bb / 32), dim3(32, 8)>>>(x);
    k_hist<<<(E0 + E1 + E2 + 255) / 256, 256>>>(e0d, e1d, e2d);
    k_scan<<<3, 1024>>>();
    k_fill<<<(E0 + E1 + E2 + 255) / 256, 256>>>(e0s, e0d, e1s, e1d, e2s, e2d);
    k_agg0<<<M0 / 4, 256>>>(W0);
    k_aggL<<<M1 / 2, 128>>>(W1, 1);
    k_aggL<<<M2 / 2, 128>>>(W2, 2);
    k_out<<<Bb, 128>>>(Wout, bout, out);
}